// round 1
// baseline (speedup 1.0000x reference)
#include <cuda_runtime.h>
#include <cstdint>

// Problem constants (fixed by dataset: B=1, N=768, C_IN=16, C_OUT=16, R=8)
#define N_PTS   768
#define C_INV   16
#define C_OUTV  16
#define R_B     8
#define S_SPLIT 8                       // b-range split per output row
#define B_PER_TASK (N_PTS / S_SPLIT)    // 96
#define ITERS   (B_PER_TASK / 4)        // 24 (4 pairs per warp-iteration)
#define TASKS   (N_PTS * S_SPLIT)       // 6144
#define ROW_F4  5                       // feature row stride in float4 (80B, bank-conflict-free)

// Scratch for stage-1 partials: G_partial[a][s][r*16+j], 768*8*128 floats = 3 MB.
// Fully overwritten every launch (no accumulate, no atomics) -> deterministic.
__device__ float g_Gp[N_PTS * S_SPLIT * (R_B * C_INV)];

// ---------------------------------------------------------------------------
// Stage 1: G_partial[a][s][r][j] = sum_{b in segment s} rbf(a,b,r) * feat[b][j]
//
// Warp layout: one warp == one task (a, s). Lane = (p, r): p = lane>>3 picks
// one of 4 b's handled per iteration, r = lane&7 picks the RBF basis.
// One sqrt.approx + one ex2.approx warp instruction covers 4 pairs x 8 r.
// Accumulation uses packed fma.rn.f32x2 (16 j-channels -> 8 FFMA2).
// ---------------------------------------------------------------------------
__global__ void __launch_bounds__(256, 1) conv_stage1(
    const float* __restrict__ feat,    // [768,16]
    const float* __restrict__ geom,    // [768,3]
    const float* __restrict__ mu,      // [8]
    const float* __restrict__ gamma)   // [8]
{
    extern __shared__ float smem[];
    float4* sFeat = (float4*)smem;                     // 768 rows * ROW_F4 float4
    float4* sGeom = (float4*)(smem + N_PTS * 20);      // 768 float4 (xyz + pad)

    const int tid = threadIdx.x;

    // Fill shared: features (padded rows) + geometry (float3 -> float4)
    const float4* feat4 = (const float4*)feat;
    for (int i = tid; i < N_PTS * 4; i += 256) {
        int b = i >> 2, c = i & 3;
        sFeat[b * ROW_F4 + c] = feat4[i];
    }
    for (int b = tid; b < N_PTS; b += 256) {
        sGeom[b] = make_float4(geom[3 * b], geom[3 * b + 1], geom[3 * b + 2], 0.f);
    }
    __syncthreads();

    const int lane = tid & 31;
    const int warp = tid >> 5;
    const int r    = lane & 7;
    const int p    = lane >> 3;

    const float negmu = -__ldg(mu + r);
    const float cexp  = -__ldg(gamma + r) * 1.44269504088896f;   // -gamma * log2(e)

    // Transposed virtual warp id so remainder tasks spread evenly across SMs.
    const int vw = warp * gridDim.x + blockIdx.x;
    const int nw = gridDim.x * 8;

    for (int task = vw; task < TASKS; task += nw) {
        const int a = task >> 3;
        const int s = task & 7;
        const float4 ga = sGeom[a];

        unsigned long long acc[8];
        #pragma unroll
        for (int k = 0; k < 8; k++) acc[k] = 0ull;

        const int b0 = s * B_PER_TASK + p;
        #pragma unroll 4
        for (int it = 0; it < ITERS; it++) {
            const int b = b0 + it * 4;
            const float4 gb = sGeom[b];
            float dx = gb.x - ga.x, dy = gb.y - ga.y, dz = gb.z - ga.z;
            float d2 = fmaf(dx, dx, 1e-9f);
            d2 = fmaf(dy, dy, d2);
            d2 = fmaf(dz, dz, d2);
            float d;
            asm("sqrt.approx.f32 %0, %1;" : "=f"(d) : "f"(d2));
            const float arg = d + negmu;
            const float t   = arg * cexp;
            const float pw  = t * arg;           // -gamma*log2e*(d-mu)^2
            float e;
            asm("ex2.approx.f32 %0, %1;" : "=f"(e) : "f"(pw));
            unsigned long long e2;
            asm("mov.b64 %0, {%1, %1};" : "=l"(e2) : "f"(e));

            const unsigned long long* row =
                (const unsigned long long*)(sFeat + b * ROW_F4);
            // ulonglong2-style 128-bit loads, packed f32x2 FMA (8 inst for 16 ch)
            #pragma unroll
            for (int k = 0; k < 8; k++) {
                unsigned long long fv = row[k];
                asm("fma.rn.f32x2 %0, %1, %2, %0;"
                    : "+l"(acc[k]) : "l"(fv), "l"(e2));
            }
        }

        // Reduce across the 4 p-groups (lane bits 3,4), still packed.
        #pragma unroll
        for (int k = 0; k < 8; k++) {
            unsigned long long o = __shfl_xor_sync(0xffffffffu, acc[k], 8);
            asm("add.rn.f32x2 %0, %0, %1;" : "+l"(acc[k]) : "l"(o));
            o = __shfl_xor_sync(0xffffffffu, acc[k], 16);
            asm("add.rn.f32x2 %0, %0, %1;" : "+l"(acc[k]) : "l"(o));
        }

        if (p == 0) {
            unsigned long long* dst =
                (unsigned long long*)g_Gp + (size_t)(a * 8 + s) * 64 + r * 8;
            #pragma unroll
            for (int k = 0; k < 8; k++) dst[k] = acc[k];
        }
    }
}

// ---------------------------------------------------------------------------
// Stage 2: out[a][i] = scale * sum_{r,j} W[r][i][j] * (sum_s Gp[a][s][r*16+j])
// One warp per output row a.
// ---------------------------------------------------------------------------
__global__ void __launch_bounds__(256, 1) conv_stage2(
    const float* __restrict__ W,       // [8,16,16]
    float scale,
    float* __restrict__ out)           // [768,16]
{
    __shared__ float sG[8][128];
    const int tid  = threadIdx.x;
    const int lane = tid & 31;
    const int warp = tid >> 5;
    const int a    = blockIdx.x * 8 + warp;

    const float4* gp = (const float4*)g_Gp;
    float4 gsum = make_float4(0.f, 0.f, 0.f, 0.f);
    #pragma unroll
    for (int s = 0; s < 8; s++) {
        float4 v = gp[(size_t)(a * 8 + s) * 32 + lane];
        gsum.x += v.x; gsum.y += v.y; gsum.z += v.z; gsum.w += v.w;
    }
    ((float4*)sG[warp])[lane] = gsum;
    __syncwarp();

    if (lane < 16) {
        const int i = lane;
        float accum = 0.f;
        #pragma unroll
        for (int rr = 0; rr < 8; rr++) {
            #pragma unroll
            for (int c = 0; c < 4; c++) {
                float4 w4 = __ldg((const float4*)W + (rr * 16 + i) * 4 + c);
                float4 g4 = ((const float4*)sG[warp])[rr * 4 + c];
                accum += w4.x * g4.x + w4.y * g4.y + w4.z * g4.z + w4.w * g4.w;
            }
        }
        out[a * 16 + i] = accum * scale;
    }
}

// ---------------------------------------------------------------------------
// Launch
// ---------------------------------------------------------------------------
extern "C" void kernel_launch(void* const* d_in, const int* in_sizes, int n_in,
                              void* d_out, int out_size)
{
    const float* feat  = (const float*)d_in[0];   // [1,768,16]
    const float* geom  = (const float*)d_in[1];   // [1,768,3]
    const float* W     = (const float*)d_in[2];   // [8,16,16]
    const float* mu    = (const float*)d_in[3];   // [8]
    const float* gamma = (const float*)d_in[4];   // [8]
    float* out = (float*)d_out;

    // n_norm == N; derive on host from geometry element count (dtype-agnostic).
    const int n_norm = in_sizes[1] / 3;
    float scale = 1.0f / sqrtf((float)n_norm);

    int sms = 148;
    cudaDeviceGetAttribute(&sms, cudaDevAttrMultiProcessorCount, 0);

    const size_t smem1 = (size_t)(N_PTS * 20 + N_PTS * 4) * sizeof(float); // 73728 B
    cudaFuncSetAttribute(conv_stage1,
                         cudaFuncAttributeMaxDynamicSharedMemorySize, (int)smem1);

    conv_stage1<<<sms, 256, smem1>>>(feat, geom, mu, gamma);
    conv_stage2<<<N_PTS / 8, 256>>>(W, scale, out);
}

// round 2
// speedup vs baseline: 1.0435x; 1.0435x over previous
#include <cuda_runtime.h>
#include <cstdint>

// Fixed problem shape: B=1, N=768, C_IN=C_OUT=16, R=8
#define N_PTS  768
#define A_GRP  3                        // output rows per block-group
#define N_GRPS (N_PTS / A_GRP)          // 256
#define NWARPS 8
#define NTHR   256
#define ITERS  (N_PTS / (NWARPS * 4))   // 24 (4 b's per warp-iteration via p)
#define ROW_F4 5                        // feature row stride in float4 (80B, conflict-free)

typedef unsigned long long ull;

// ---------------------------------------------------------------------------
// Single fused kernel.
//   Lane layout: lane = p*8 + r  (p = b-slot 0..3, r = RBF basis 0..7).
//   Each warp-iteration handles 4 b's x 3 a's x 8 r x 16 channels.
//   Per (a, 4b): 1 sqrt.approx + 1 ex2.approx warp instruction;
//   accumulation via packed fma.rn.f32x2 (8 inst per a for 16 channels).
//   Epilogue: shfl-reduce over p, smem-reduce over warps, contract with W,
//   write out[a][0..15] directly. No global scratch.
// ---------------------------------------------------------------------------
__global__ void __launch_bounds__(NTHR, 1) conv_fused(
    const float* __restrict__ feat,    // [768,16]
    const float* __restrict__ geom,    // [768,3]
    const float* __restrict__ W,       // [8,16,16]
    const float* __restrict__ mu,      // [8]
    const float* __restrict__ gamma,   // [8]
    float scale,
    float* __restrict__ out)           // [768,16]
{
    extern __shared__ float smem[];
    float4* sFeat = (float4*)smem;                        // 768 * 5 float4 (padded rows)
    float4* sGeom = (float4*)(smem + N_PTS * 20);         // 768 float4
    float*  sW    = smem + N_PTS * 20 + N_PTS * 4;        // 2048 floats
    ull*    sRed  = (ull*)(sW + 2048);                    // A_GRP*8*9*8 = 1728 ull (pad 9)
    float*  sGbuf = (float*)(sRed + A_GRP * 8 * 9 * 8);   // A_GRP * 128 floats

    const int tid = threadIdx.x;

    // ---- fill shared ----
    const float4* feat4 = (const float4*)feat;
    for (int i = tid; i < N_PTS * 4; i += NTHR)
        sFeat[(i >> 2) * ROW_F4 + (i & 3)] = feat4[i];
    for (int b = tid; b < N_PTS; b += NTHR)
        sGeom[b] = make_float4(geom[3 * b], geom[3 * b + 1], geom[3 * b + 2], 0.f);
    for (int i = tid; i < 2048; i += NTHR)
        sW[i] = W[i];
    __syncthreads();

    const int lane = tid & 31;
    const int warp = tid >> 5;
    const int r    = lane & 7;
    const int p    = lane >> 3;

    // RBF constants per lane:  pw = -(kr*d + mr)^2 = -gamma*log2(e)*(d-mu)^2
    const float kr = sqrtf(__ldg(gamma + r) * 1.44269504088896f);
    const float mr = -__ldg(mu + r) * kr;

    const int bbase = warp * 4 + p;

    for (int g = blockIdx.x; g < N_GRPS; g += gridDim.x) {
        const int a0 = g * A_GRP;

        float gax[A_GRP], gay[A_GRP], gaz[A_GRP];
        #pragma unroll
        for (int ai = 0; ai < A_GRP; ai++) {
            float4 ga = sGeom[a0 + ai];
            gax[ai] = ga.x; gay[ai] = ga.y; gaz[ai] = ga.z;
        }

        ull acc[A_GRP][8];
        #pragma unroll
        for (int ai = 0; ai < A_GRP; ai++)
            #pragma unroll
            for (int k = 0; k < 8; k++) acc[ai][k] = 0ull;

        #pragma unroll 4
        for (int it = 0; it < ITERS; it++) {
            const int b = bbase + it * 32;
            const float4 gb = sGeom[b];
            const ull* row = (const ull*)(sFeat + b * ROW_F4);
            ull rv[8];
            #pragma unroll
            for (int k = 0; k < 8; k++) rv[k] = row[k];   // hoist: 8 LDS.64, high MLP

            #pragma unroll
            for (int ai = 0; ai < A_GRP; ai++) {
                float dx = gb.x - gax[ai];
                float dy = gb.y - gay[ai];
                float dz = gb.z - gaz[ai];
                float d2 = fmaf(dx, dx, 1e-9f);
                d2 = fmaf(dy, dy, d2);
                d2 = fmaf(dz, dz, d2);
                float d;
                asm("sqrt.approx.f32 %0, %1;" : "=f"(d) : "f"(d2));
                float v  = fmaf(d, kr, mr);
                float pw = v * (-v);
                float e;
                asm("ex2.approx.f32 %0, %1;" : "=f"(e) : "f"(pw));
                ull e2;
                asm("mov.b64 %0, {%1, %1};" : "=l"(e2) : "f"(e));
                #pragma unroll
                for (int k = 0; k < 8; k++)
                    asm("fma.rn.f32x2 %0, %1, %2, %0;"
                        : "+l"(acc[ai][k]) : "l"(rv[k]), "l"(e2));
            }
        }

        // ---- reduce over p (lane bits 3,4), packed ----
        #pragma unroll
        for (int ai = 0; ai < A_GRP; ai++)
            #pragma unroll
            for (int k = 0; k < 8; k++) {
                ull o = __shfl_xor_sync(0xffffffffu, acc[ai][k], 8);
                asm("add.rn.f32x2 %0, %0, %1;" : "+l"(acc[ai][k]) : "l"(o));
                o = __shfl_xor_sync(0xffffffffu, acc[ai][k], 16);
                asm("add.rn.f32x2 %0, %0, %1;" : "+l"(acc[ai][k]) : "l"(o));
            }

        // ---- stash per-warp partials: sRed[ai][r][warp][8 ull] (pad 9) ----
        if (p == 0) {
            #pragma unroll
            for (int ai = 0; ai < A_GRP; ai++) {
                ull* dst = sRed + ((ai * 8 + r) * 9 + warp) * 8;
                #pragma unroll
                for (int k = 0; k < 8; k++) dst[k] = acc[ai][k];
            }
        }
        __syncthreads();

        // ---- cross-warp reduce + W contraction: warp ai owns row a0+ai ----
        if (warp < A_GRP) {
            const int ai = warp;
            const int rr = lane >> 2;
            const int jp = (lane & 3) * 2;       // ull offset within the 8-ull row
            ull s0 = 0ull, s1 = 0ull;
            #pragma unroll
            for (int w = 0; w < NWARPS; w++) {
                const ull* src = sRed + ((ai * 8 + rr) * 9 + w) * 8 + jp;
                asm("add.rn.f32x2 %0, %0, %1;" : "+l"(s0) : "l"(src[0]));
                asm("add.rn.f32x2 %0, %0, %1;" : "+l"(s1) : "l"(src[1]));
            }
            ull* gdst = (ull*)(sGbuf + ai * 128);
            gdst[lane * 2]     = s0;             // ull idx 2*lane == r*8 + jp
            gdst[lane * 2 + 1] = s1;
            __syncwarp();

            if (lane < 16) {
                const int i = lane;
                float accum = 0.f;
                const float4* wv = (const float4*)sW;
                const float4* gv = (const float4*)(sGbuf + ai * 128);
                #pragma unroll
                for (int r2 = 0; r2 < 8; r2++)
                    #pragma unroll
                    for (int c = 0; c < 4; c++) {
                        float4 w4 = wv[(r2 * 16 + i) * 4 + c];
                        float4 g4 = gv[r2 * 4 + c];
                        accum = fmaf(w4.x, g4.x, accum);
                        accum = fmaf(w4.y, g4.y, accum);
                        accum = fmaf(w4.z, g4.z, accum);
                        accum = fmaf(w4.w, g4.w, accum);
                    }
                out[(a0 + ai) * 16 + i] = accum * scale;
            }
        }
        __syncthreads();   // protect sRed/sGbuf reuse next group
    }
}

// ---------------------------------------------------------------------------
// Launch: single kernel, no scratch, graph-capturable.
// ---------------------------------------------------------------------------
extern "C" void kernel_launch(void* const* d_in, const int* in_sizes, int n_in,
                              void* d_out, int out_size)
{
    const float* feat  = (const float*)d_in[0];   // [1,768,16]
    const float* geom  = (const float*)d_in[1];   // [1,768,3]
    const float* W     = (const float*)d_in[2];   // [8,16,16]
    const float* mu    = (const float*)d_in[3];   // [8]
    const float* gamma = (const float*)d_in[4];   // [8]
    float* out = (float*)d_out;

    const int n_norm = in_sizes[1] / 3;           // N, host-side (dtype-agnostic)
    const float scale = 1.0f / sqrtf((float)n_norm);

    int sms = 148;
    cudaDeviceGetAttribute(&sms, cudaDevAttrMultiProcessorCount, 0);
    int grid = sms < N_GRPS ? sms : N_GRPS;

    const size_t smem_bytes =
        (size_t)(N_PTS * 20 + N_PTS * 4 + 2048) * sizeof(float)   // feat+geom+W
        + (size_t)(A_GRP * 8 * 9 * 8) * sizeof(ull)               // sRed
        + (size_t)(A_GRP * 128) * sizeof(float);                  // sGbuf
    cudaFuncSetAttribute(conv_fused,
                         cudaFuncAttributeMaxDynamicSharedMemorySize,
                         (int)smem_bytes);

    conv_fused<<<grid, NTHR, smem_bytes>>>(feat, geom, W, mu, gamma, scale, out);
}